// round 15
// baseline (speedup 1.0000x reference)
#include <cuda_runtime.h>
#include <math_constants.h>

// Problem dims
#define BATCH 64
#define DIM   768
#define MEM   2048
#define NCLS  1000

#define EC  48                 // e-chunk per score block (DIM/EC = 16)
#define NEC (DIM / EC)
#define KC  16                 // gemm k-chunk

// Scratch (allocation-free)
__device__ float g_q[BATCH * DIM];
__device__ float g_t[BATCH * DIM];
__device__ float g_scores[BATCH * MEM];
__device__ unsigned g_rowdone[BATCH];   // monotonic; exactly 32 arrivals/row/launch

// ---------------------------------------------------------------------------
// Zero scratch: g_q, g_t (GEMM atomic targets) and g_scores (score atomics).
// 57344 float4 stores -> 112 blocks x 512 threads.
// ---------------------------------------------------------------------------
__global__ void zero_scratch() {
    const int i = blockIdx.x * 512 + threadIdx.x;
    const float4 z = make_float4(0.f, 0.f, 0.f, 0.f);
    if (i < BATCH * DIM / 4) {
        ((float4*)g_q)[i] = z;
        ((float4*)g_t)[i] = z;
    }
    if (i < BATCH * MEM / 4) ((float4*)g_scores)[i] = z;
    cudaTriggerProgrammaticLaunchCompletion();
}

// ---------------------------------------------------------------------------
// GEMM stage: C[64,768] += A[64,768] @ W[768,768]  (row-major, split-K)
// grid = (6 j-tiles of 128, 48 k-chunks of 16), block = 256 threads.
// Thread: 4 consecutive j (float4 W load) x 8 b (smem broadcast), 8x W reuse.
// PDL: stage 0 syncs right before its atomics (compute overlaps zero kernel);
// stage 1 reads g_q so it syncs up front.
// ---------------------------------------------------------------------------
__global__ void __launch_bounds__(256) gemm_stage(const float* __restrict__ Aext,
                                                  const float* __restrict__ W,
                                                  int stage) {
    if (stage != 0) cudaGridDependencySynchronize();  // wait for g_q

    const float* A = (stage == 0) ? Aext : g_q;
    float* Cc      = (stage == 0) ? g_q  : g_t;

    __shared__ float xs[KC][BATCH + 1];

    const int k0 = blockIdx.y * KC;

    for (int i = threadIdx.x; i < BATCH * KC; i += 256) {
        int b = i >> 4;          // i / 16
        int d = i & (KC - 1);    // i % 16
        xs[d][b] = A[b * DIM + k0 + d];
    }
    __syncthreads();

    const int jv = threadIdx.x & 31;
    const int bg = threadIdx.x >> 5;
    const int j  = blockIdx.x * 128 + jv * 4;

    float acc[8][4];
    #pragma unroll
    for (int bb = 0; bb < 8; bb++)
        #pragma unroll
        for (int jj = 0; jj < 4; jj++) acc[bb][jj] = 0.0f;

    #pragma unroll
    for (int d = 0; d < KC; d++) {
        const float4 w = *(const float4*)&W[(size_t)(k0 + d) * DIM + j];
        #pragma unroll
        for (int bb = 0; bb < 8; bb++) {
            const float xv = xs[d][bg * 8 + bb];
            acc[bb][0] = fmaf(xv, w.x, acc[bb][0]);
            acc[bb][1] = fmaf(xv, w.y, acc[bb][1]);
            acc[bb][2] = fmaf(xv, w.z, acc[bb][2]);
            acc[bb][3] = fmaf(xv, w.w, acc[bb][3]);
        }
    }

    if (stage == 0) cudaGridDependencySynchronize();  // zero of g_q must be done

    #pragma unroll
    for (int bb = 0; bb < 8; bb++) {
        const int b = bg * 8 + bb;
        atomicAdd(&Cc[b * DIM + j + 0], acc[bb][0]);
        atomicAdd(&Cc[b * DIM + j + 1], acc[bb][1]);
        atomicAdd(&Cc[b * DIM + j + 2], acc[bb][2]);
        atomicAdd(&Cc[b * DIM + j + 3], acc[bb][3]);
    }
    cudaTriggerProgrammaticLaunchCompletion();
}

// ---------------------------------------------------------------------------
// Row epilogue (run by the 32nd-finishing score block of row b):
// leaky-relu(g_scores[b,:]) scattered into shared logits[1000] (smem atomics),
// softmax, write out[b,:]. 256 threads.
// Label dtype: int64 labels in [0,1000) have all-zero odd 32-bit words.
// ---------------------------------------------------------------------------
__device__ void epilogue_row(int b, const int* __restrict__ lab32,
                             float* __restrict__ out) {
    const int tid = threadIdx.x;
    __shared__ float logits[NCLS];
    __shared__ float red[8];
    __shared__ int   sh_is64;

    for (int i = tid; i < NCLS; i += 256) logits[i] = 0.0f;
    if (tid == 0) {
        int any = 0;
        #pragma unroll
        for (int k = 0; k < 32; k++) any |= lab32[2 * k + 1];
        sh_is64 = (any == 0) ? 1 : 0;
    }
    __syncthreads();
    const int is64 = sh_is64;

    for (int i = tid; i < MEM; i += 256) {
        const size_t idx = (size_t)b * MEM + i;
        const float s = __ldcg(&g_scores[idx]);   // L2 (atomic-written)
        const float sv = (s >= 0.0f) ? s : 0.01f * s;
        int lab = is64 ? lab32[2 * idx] : lab32[idx];
        lab = min(max(lab, 0), NCLS - 1);
        atomicAdd(&logits[lab], sv);
    }
    __syncthreads();

    // --- max ---
    float mx = -CUDART_INF_F;
    for (int i = tid; i < NCLS; i += 256) mx = fmaxf(mx, logits[i]);
    #pragma unroll
    for (int o = 16; o > 0; o >>= 1) mx = fmaxf(mx, __shfl_xor_sync(0xffffffffu, mx, o));
    if ((tid & 31) == 0) red[tid >> 5] = mx;
    __syncthreads();
    if (tid < 32) {
        float v = (tid < 8) ? red[tid] : -CUDART_INF_F;
        #pragma unroll
        for (int o = 4; o > 0; o >>= 1) v = fmaxf(v, __shfl_xor_sync(0xffffffffu, v, o));
        if (tid == 0) red[0] = v;
    }
    __syncthreads();
    mx = red[0];
    __syncthreads();

    // --- exp + sum ---
    float sum = 0.0f;
    for (int i = tid; i < NCLS; i += 256) {
        const float e = __expf(logits[i] - mx);
        logits[i] = e;
        sum += e;
    }
    #pragma unroll
    for (int o = 16; o > 0; o >>= 1) sum += __shfl_xor_sync(0xffffffffu, sum, o);
    if ((tid & 31) == 0) red[tid >> 5] = sum;
    __syncthreads();
    if (tid < 32) {
        float v = (tid < 8) ? red[tid] : 0.0f;
        #pragma unroll
        for (int o = 4; o > 0; o >>= 1) v += __shfl_xor_sync(0xffffffffu, v, o);
        if (tid == 0) red[0] = v;
    }
    __syncthreads();
    const float inv = 1.0f / red[0];

    for (int i = tid; i < NCLS; i += 256) out[b * NCLS + i] = logits[i] * inv;
}

// ---------------------------------------------------------------------------
// Dominant kernel (proven streaming config) + fused row epilogue:
// scores[b,m] += sum_{e in chunk} t[b,e]*mem[b,e,m]; then a row-completion
// ticket — the 32nd block of row b (2 m-tiles x 16 e-chunks) runs the
// epilogue for that row, overlapping other rows' streaming tails.
// grid = (2, 16, 64) = 2048 blocks x 256 threads.
// ---------------------------------------------------------------------------
__global__ void __launch_bounds__(256) score_epilogue(const float* __restrict__ mem,
                                                      const int* __restrict__ lab32,
                                                      float* __restrict__ out) {
    const int b  = blockIdx.z;
    const int e0 = blockIdx.y * EC;
    const int m  = blockIdx.x * 1024 + threadIdx.x * 4;
    const float4* mp = (const float4*)(mem + (size_t)b * DIM * MEM
                                           + (size_t)e0 * MEM + m);

    cudaGridDependencySynchronize();   // g_t + zeroed g_scores ready

    __shared__ float ts[EC];
    if (threadIdx.x < EC) ts[threadIdx.x] = g_t[b * DIM + e0 + threadIdx.x];
    __syncthreads();

    float ax = 0.f, ay = 0.f, az = 0.f, aw = 0.f;
    #pragma unroll 8
    for (int e = 0; e < EC; e++) {
        const float4 v = __ldcs(&mp[(size_t)e * (MEM / 4)]);
        const float w = ts[e];  // warp-uniform broadcast
        ax = fmaf(w, v.x, ax);
        ay = fmaf(w, v.y, ay);
        az = fmaf(w, v.z, az);
        aw = fmaf(w, v.w, aw);
    }

    float* sp = &g_scores[b * MEM + m];
    atomicAdd(sp + 0, ax);
    atomicAdd(sp + 1, ay);
    atomicAdd(sp + 2, az);
    atomicAdd(sp + 3, aw);

    // ---- row-completion ticket: no waiting, just one atomic + branch ----
    __threadfence();                    // scores visible before ticket
    __syncthreads();                    // whole block done with its adds
    __shared__ int winner;
    if (threadIdx.x == 0) {
        const unsigned t = atomicAdd(&g_rowdone[b], 1u);
        winner = ((t & 31u) == 31u) ? 1 : 0;   // 32nd of 32 blocks this replay
    }
    __syncthreads();
    if (winner) epilogue_row(b, lab32, out);
}

// ---------------------------------------------------------------------------
// Launch (4 nodes): zero -> gemm1 (PDL) -> gemm2 (PDL) -> score+epi (PDL).
// Inputs mapped by element count: x 49152, mem 100663296, labels 131072,
// W_Q / W_K 589824 each (W_Q first).  Output: f32[64,1000].
// ---------------------------------------------------------------------------
template <typename... Args>
static inline void launch_pdl(void (*kern)(Args...), dim3 grid, dim3 block,
                              Args... args) {
    cudaLaunchConfig_t cfg = {};
    cfg.gridDim = grid;
    cfg.blockDim = block;
    cfg.dynamicSmemBytes = 0;
    cfg.stream = 0;
    cudaLaunchAttribute attr[1];
    attr[0].id = cudaLaunchAttributeProgrammaticStreamSerialization;
    attr[0].val.programmaticStreamSerializationAllowed = 1;
    cfg.attrs = attr;
    cfg.numAttrs = 1;
    cudaLaunchKernelEx(&cfg, kern, args...);
}

extern "C" void kernel_launch(void* const* d_in, const int* in_sizes, int n_in,
                              void* d_out, int out_size) {
    const float* x   = nullptr;
    const float* mem = nullptr;
    const int* labs  = nullptr;
    const float* W_Q = nullptr;
    const float* W_K = nullptr;

    for (int i = 0; i < n_in; i++) {
        const int sz = in_sizes[i];
        if (sz == BATCH * DIM)            x    = (const float*)d_in[i];
        else if (sz == BATCH * DIM * MEM) mem  = (const float*)d_in[i];
        else if (sz == BATCH * MEM)       labs = (const int*)d_in[i];
        else if (sz == DIM * DIM) {
            if (!W_Q) W_Q = (const float*)d_in[i];
            else      W_K = (const float*)d_in[i];
        }
    }
    float* out = (float*)d_out;

    zero_scratch<<<112, 512>>>();
    launch_pdl(gemm_stage, dim3(DIM / 128, DIM / KC), dim3(256), x, W_K, 0);
    launch_pdl(gemm_stage, dim3(DIM / 128, DIM / KC), dim3(256), x, W_Q, 1);
    launch_pdl(score_epilogue, dim3(2, NEC, BATCH), dim3(256), mem, labs, out);
}

// round 16
// speedup vs baseline: 1.1235x; 1.1235x over previous
#include <cuda_runtime.h>
#include <math_constants.h>

// Problem dims
#define BATCH 64
#define DIM   768
#define MEM   2048
#define NCLS  1000

#define EC  48                 // e-chunk per score block (DIM/EC = 16)
#define NEC (DIM / EC)
#define KC  16                 // gemm k-chunk
#define PF  8                  // e-rows prefetched into L2 pre-sync

// Scratch (allocation-free)
__device__ float g_q[BATCH * DIM];
__device__ float g_t[BATCH * DIM];
__device__ float g_scores[BATCH * MEM];

// ---------------------------------------------------------------------------
// Zero scratch: g_q, g_t (GEMM atomic targets) and g_scores (score atomics).
// 57344 float4 stores -> 112 blocks x 512 threads. Trigger at top: lets the
// rest of the chain launch immediately (consumers gate on gridDepSync).
// ---------------------------------------------------------------------------
__global__ void zero_scratch() {
    cudaTriggerProgrammaticLaunchCompletion();
    const int i = blockIdx.x * 512 + threadIdx.x;
    const float4 z = make_float4(0.f, 0.f, 0.f, 0.f);
    if (i < BATCH * DIM / 4) {
        ((float4*)g_q)[i] = z;
        ((float4*)g_t)[i] = z;
    }
    if (i < BATCH * MEM / 4) ((float4*)g_scores)[i] = z;
}

// ---------------------------------------------------------------------------
// GEMM stage: C[64,768] += A[64,768] @ W[768,768]  (row-major, split-K)
// grid = (6 j-tiles of 128, 48 k-chunks of 16), block = 256 threads.
// Thread: 4 consecutive j (float4 W load) x 8 b (smem broadcast), 8x W reuse.
// PDL: early trigger (top); stage 0 syncs right before its atomics, stage 1
// syncs before reading g_q. Correctness rides on gridDepSync only.
// ---------------------------------------------------------------------------
__global__ void __launch_bounds__(256) gemm_stage(const float* __restrict__ Aext,
                                                  const float* __restrict__ W,
                                                  int stage) {
    cudaTriggerProgrammaticLaunchCompletion();
    if (stage != 0) cudaGridDependencySynchronize();  // wait for g_q

    const float* A = (stage == 0) ? Aext : g_q;
    float* Cc      = (stage == 0) ? g_q  : g_t;

    __shared__ float xs[KC][BATCH + 1];

    const int k0 = blockIdx.y * KC;

    for (int i = threadIdx.x; i < BATCH * KC; i += 256) {
        int b = i >> 4;          // i / 16
        int d = i & (KC - 1);    // i % 16
        xs[d][b] = A[b * DIM + k0 + d];
    }
    __syncthreads();

    const int jv = threadIdx.x & 31;
    const int bg = threadIdx.x >> 5;
    const int j  = blockIdx.x * 128 + jv * 4;

    float acc[8][4];
    #pragma unroll
    for (int bb = 0; bb < 8; bb++)
        #pragma unroll
        for (int jj = 0; jj < 4; jj++) acc[bb][jj] = 0.0f;

    #pragma unroll
    for (int d = 0; d < KC; d++) {
        const float4 w = *(const float4*)&W[(size_t)(k0 + d) * DIM + j];
        #pragma unroll
        for (int bb = 0; bb < 8; bb++) {
            const float xv = xs[d][bg * 8 + bb];
            acc[bb][0] = fmaf(xv, w.x, acc[bb][0]);
            acc[bb][1] = fmaf(xv, w.y, acc[bb][1]);
            acc[bb][2] = fmaf(xv, w.z, acc[bb][2]);
            acc[bb][3] = fmaf(xv, w.w, acc[bb][3]);
        }
    }

    if (stage == 0) cudaGridDependencySynchronize();  // zero of g_q must be done

    #pragma unroll
    for (int bb = 0; bb < 8; bb++) {
        const int b = bg * 8 + bb;
        atomicAdd(&Cc[b * DIM + j + 0], acc[bb][0]);
        atomicAdd(&Cc[b * DIM + j + 1], acc[bb][1]);
        atomicAdd(&Cc[b * DIM + j + 2], acc[bb][2]);
        atomicAdd(&Cc[b * DIM + j + 3], acc[bb][3]);
    }
}

// ---------------------------------------------------------------------------
// Dominant kernel (proven config): scores[b,m] += sum_e t[b,e]*mem[b,e,m].
// Streams 402 MB once. grid = (2, 16, 64) = 2048 blocks x 256 threads.
// NEW: pre-sync L2 prefetch of the first PF e-rows — runs while the gemms
// are still executing (idle DRAM), so ~37 MB of the stream leaves the
// critical window. Same total DRAM bytes; hot loop unchanged.
// ---------------------------------------------------------------------------
__global__ void __launch_bounds__(256) score_partial(const float* __restrict__ mem) {
    cudaTriggerProgrammaticLaunchCompletion();

    const int b  = blockIdx.z;
    const int e0 = blockIdx.y * EC;
    const int m  = blockIdx.x * 1024 + threadIdx.x * 4;
    const float4* mp = (const float4*)(mem + (size_t)b * DIM * MEM
                                           + (size_t)e0 * MEM + m);

    // Pre-sync: pull first PF e-rows of this block's slice into L2.
    #pragma unroll
    for (int e = 0; e < PF; e++)
        asm volatile("prefetch.global.L2 [%0];" :: "l"(mp + (size_t)e * (MEM / 4)));

    cudaGridDependencySynchronize();   // g_t + zeroed g_scores ready

    __shared__ float ts[EC];
    if (threadIdx.x < EC) ts[threadIdx.x] = g_t[b * DIM + e0 + threadIdx.x];
    __syncthreads();

    float ax = 0.f, ay = 0.f, az = 0.f, aw = 0.f;
    #pragma unroll 8
    for (int e = 0; e < EC; e++) {
        const float4 v = __ldcs(&mp[(size_t)e * (MEM / 4)]);
        const float w = ts[e];  // warp-uniform broadcast
        ax = fmaf(w, v.x, ax);
        ay = fmaf(w, v.y, ay);
        az = fmaf(w, v.z, az);
        aw = fmaf(w, v.w, aw);
    }

    float* sp = &g_scores[b * MEM + m];
    atomicAdd(sp + 0, ax);
    atomicAdd(sp + 1, ay);
    atomicAdd(sp + 2, az);
    atomicAdd(sp + 3, aw);
}

// ---------------------------------------------------------------------------
// Fused epilogue: leaky-relu(scores) scattered into shared logits[1000]
// (smem atomics), then softmax -> out[b, :]. 64 blocks x 512 threads.
// PDL: logits zero + label-dtype detect pre-sync (overlaps score tail).
// Label dtype: int64 labels in [0,1000) have all-zero odd 32-bit words.
// ---------------------------------------------------------------------------
__global__ void __launch_bounds__(512) epilogue(const int* __restrict__ lab32,
                                                float* __restrict__ out) {
    const int b = blockIdx.x;
    const int tid = threadIdx.x;

    __shared__ float logits[NCLS];
    __shared__ float red[16];
    __shared__ int   sh_is64;

    for (int i = tid; i < NCLS; i += 512) logits[i] = 0.0f;
    if (tid == 0) {
        int any = 0;
        #pragma unroll
        for (int k = 0; k < 32; k++) any |= lab32[2 * k + 1];
        sh_is64 = (any == 0) ? 1 : 0;
    }
    __syncthreads();
    const int is64 = sh_is64;

    cudaGridDependencySynchronize();   // g_scores complete

    for (int i = tid; i < MEM; i += 512) {
        const size_t idx = (size_t)b * MEM + i;
        const float s = g_scores[idx];
        const float sv = (s >= 0.0f) ? s : 0.01f * s;
        int lab = is64 ? lab32[2 * idx] : lab32[idx];
        lab = min(max(lab, 0), NCLS - 1);
        atomicAdd(&logits[lab], sv);
    }
    __syncthreads();

    // --- max ---
    float mx = -CUDART_INF_F;
    for (int i = tid; i < NCLS; i += 512) mx = fmaxf(mx, logits[i]);
    #pragma unroll
    for (int o = 16; o > 0; o >>= 1) mx = fmaxf(mx, __shfl_xor_sync(0xffffffffu, mx, o));
    if ((tid & 31) == 0) red[tid >> 5] = mx;
    __syncthreads();
    if (tid < 32) {
        float v = (tid < 16) ? red[tid] : -CUDART_INF_F;
        #pragma unroll
        for (int o = 8; o > 0; o >>= 1) v = fmaxf(v, __shfl_xor_sync(0xffffffffu, v, o));
        if (tid == 0) red[0] = v;
    }
    __syncthreads();
    mx = red[0];
    __syncthreads();

    // --- exp + sum ---
    float sum = 0.0f;
    for (int i = tid; i < NCLS; i += 512) {
        const float e = __expf(logits[i] - mx);
        logits[i] = e;
        sum += e;
    }
    #pragma unroll
    for (int o = 16; o > 0; o >>= 1) sum += __shfl_xor_sync(0xffffffffu, sum, o);
    if ((tid & 31) == 0) red[tid >> 5] = sum;
    __syncthreads();
    if (tid < 32) {
        float v = (tid < 16) ? red[tid] : 0.0f;
        #pragma unroll
        for (int o = 8; o > 0; o >>= 1) v += __shfl_xor_sync(0xffffffffu, v, o);
        if (tid == 0) red[0] = v;
    }
    __syncthreads();
    const float inv = 1.0f / red[0];

    for (int i = tid; i < NCLS; i += 512) out[b * NCLS + i] = logits[i] * inv;
}

// ---------------------------------------------------------------------------
// Launch chain with PDL on every edge (proven 90.5us structure + prefetch):
// zero -> gemm1 -> gemm2 -> score -> epilogue.
// Inputs mapped by element count: x 49152, mem 100663296, labels 131072,
// W_Q / W_K 589824 each (W_Q first).  Output: f32[64,1000].
// ---------------------------------------------------------------------------
template <typename... Args>
static inline void launch_pdl(void (*kern)(Args...), dim3 grid, dim3 block,
                              Args... args) {
    cudaLaunchConfig_t cfg = {};
    cfg.gridDim = grid;
    cfg.blockDim = block;
    cfg.dynamicSmemBytes = 0;
    cfg.stream = 0;
    cudaLaunchAttribute attr[1];
    attr[0].id = cudaLaunchAttributeProgrammaticStreamSerialization;
    attr[0].val.programmaticStreamSerializationAllowed = 1;
    cfg.attrs = attr;
    cfg.numAttrs = 1;
    cudaLaunchKernelEx(&cfg, kern, args...);
}

extern "C" void kernel_launch(void* const* d_in, const int* in_sizes, int n_in,
                              void* d_out, int out_size) {
    const float* x   = nullptr;
    const float* mem = nullptr;
    const int* labs  = nullptr;
    const float* W_Q = nullptr;
    const float* W_K = nullptr;

    for (int i = 0; i < n_in; i++) {
        const int sz = in_sizes[i];
        if (sz == BATCH * DIM)            x    = (const float*)d_in[i];
        else if (sz == BATCH * DIM * MEM) mem  = (const float*)d_in[i];
        else if (sz == BATCH * MEM)       labs = (const int*)d_in[i];
        else if (sz == DIM * DIM) {
            if (!W_Q) W_Q = (const float*)d_in[i];
            else      W_K = (const float*)d_in[i];
        }
    }
    float* out = (float*)d_out;

    zero_scratch<<<112, 512>>>();
    launch_pdl(gemm_stage, dim3(DIM / 128, DIM / KC), dim3(256), x, W_K, 0);
    launch_pdl(gemm_stage, dim3(DIM / 128, DIM / KC), dim3(256), x, W_Q, 1);
    launch_pdl(score_partial, dim3(2, NEC, BATCH), dim3(256), mem);
    launch_pdl(epilogue, dim3(BATCH), dim3(512), labs, out);
}